// round 12
// baseline (speedup 1.0000x reference)
#include <cuda_runtime.h>
#include <cuda_bf16.h>
#include <math.h>

#define T_TOKENS 8192
#define HID      1024
#define NE       64
#define TOPK     8
#define INTER    512
#define TK       (T_TOKENS * TOPK)     // 65536 (token, expert) pairs
#define TILE_M   64
#define MAX_TILES (TK / TILE_M + NE)   // 1088

typedef __nv_bfloat16 bf16;

// ----------------------------------------------------------------------------
// Tiny device globals only (~1 MiB): the harness memory guard counts lazily
// committed statics, so all large scratch lives in SMEM of the fused kernel.
// ----------------------------------------------------------------------------
__device__ int   g_indices[TK];
__device__ float g_rweight[TK];
__device__ int   g_row_token[TK];      // slot -> token
__device__ float g_slot_w[TK];         // slot -> routing weight
__device__ int   g_counts[NE];
__device__ int   g_fill[NE];
__device__ int   g_offsets[NE + 1];
__device__ int   g_tile_off[NE + 1];   // 64-row tiles
__device__ int   g_total_tiles;

// ----------------------------------------------------------------------------
__global__ void init_kernel() {
    int i = threadIdx.x;
    if (i < NE) { g_counts[i] = 0; g_fill[i] = 0; }
}

__global__ void zero_out_kernel(float* __restrict__ out) {
    size_t i = (size_t)blockIdx.x * blockDim.x + threadIdx.x;
    *(float4*)&out[i * 4] = make_float4(0.f, 0.f, 0.f, 0.f);
}

// ----------------------------------------------------------------------------
// fp32 pair -> bf16 hi-pair u32 + bf16 residual-pair u32
// ----------------------------------------------------------------------------
__device__ __forceinline__ void split_pack(float a, float b,
                                           unsigned& hi, unsigned& lo) {
    __nv_bfloat162 h = __float22bfloat162_rn(make_float2(a, b));
    float2 hf = __bfloat1622float2(h);
    __nv_bfloat162 l = __float22bfloat162_rn(make_float2(a - hf.x, b - hf.y));
    hi = *(unsigned*)&h;
    lo = *(unsigned*)&l;
}

// ----------------------------------------------------------------------------
// Router (fp32, exact): logits -> top8 -> softmax over top8
// ----------------------------------------------------------------------------
__global__ void __launch_bounds__(256) router_kernel(const float* __restrict__ x,
                                                     const float* __restrict__ rw) {
    __shared__ float Xs[16][128];
    __shared__ float RWs[128][64];
    __shared__ float Ls[16][64];

    int tid = threadIdx.x;
    int t0  = blockIdx.x * 16;
    int e   = tid & 63;
    int tg  = tid >> 6;

    float acc0 = 0.f, acc1 = 0.f, acc2 = 0.f, acc3 = 0.f;

    for (int h0 = 0; h0 < HID; h0 += 128) {
        #pragma unroll
        for (int r = 0; r < 2; r++) {
            int f = tid + 256 * r;
            int tok = f >> 5, c4 = f & 31;
            *(float4*)&Xs[tok][c4 * 4] =
                *(const float4*)&x[(size_t)(t0 + tok) * HID + h0 + c4 * 4];
        }
        #pragma unroll
        for (int r = 0; r < 8; r++) {
            int f = tid + 256 * r;
            int hh = f >> 4, e4 = f & 15;
            *(float4*)&RWs[hh][e4 * 4] =
                *(const float4*)&rw[(size_t)(h0 + hh) * NE + e4 * 4];
        }
        __syncthreads();
        #pragma unroll 4
        for (int hh = 0; hh < 128; hh++) {
            float w = RWs[hh][e];
            acc0 += Xs[tg * 4 + 0][hh] * w;
            acc1 += Xs[tg * 4 + 1][hh] * w;
            acc2 += Xs[tg * 4 + 2][hh] * w;
            acc3 += Xs[tg * 4 + 3][hh] * w;
        }
        __syncthreads();
    }
    Ls[tg * 4 + 0][e] = acc0;
    Ls[tg * 4 + 1][e] = acc1;
    Ls[tg * 4 + 2][e] = acc2;
    Ls[tg * 4 + 3][e] = acc3;
    __syncthreads();

    if (tid < 16) {
        int t = tid;
        int   idx[TOPK];
        float val[TOPK];
        #pragma unroll
        for (int k = 0; k < TOPK; k++) {
            float best = -1e30f; int bi = 0;
            for (int ee = 0; ee < NE; ee++) {
                float v = Ls[t][ee];
                if (v > best) { best = v; bi = ee; }
            }
            idx[k] = bi; val[k] = best;
            Ls[t][bi] = -1e30f;
        }
        float m = val[0], s = 0.f, w[TOPK];
        #pragma unroll
        for (int k = 0; k < TOPK; k++) { w[k] = expf(val[k] - m); s += w[k]; }
        float inv = 1.f / s;
        int base = (t0 + t) * TOPK;
        #pragma unroll
        for (int k = 0; k < TOPK; k++) {
            g_indices[base + k] = idx[k];
            g_rweight[base + k] = w[k] * inv;
            atomicAdd(&g_counts[idx[k]], 1);
        }
    }
}

// ----------------------------------------------------------------------------
__global__ void scan_kernel() {
    int off = 0, toff = 0;
    g_offsets[0] = 0; g_tile_off[0] = 0;
    for (int e = 0; e < NE; e++) {
        off  += g_counts[e];               g_offsets[e + 1]  = off;
        toff += (g_counts[e] + 63) >> 6;   g_tile_off[e + 1] = toff;
    }
    g_total_tiles = toff;
}

__global__ void scatter_kernel() {
    int i = blockIdx.x * blockDim.x + threadIdx.x;
    if (i >= TK) return;
    int e    = g_indices[i];
    int pos  = atomicAdd(&g_fill[e], 1);
    int slot = g_offsets[e] + pos;
    g_row_token[slot] = i >> 3;
    g_slot_w[slot]    = g_rweight[i];
}

// ----------------------------------------------------------------------------
// MMA / LDSM primitives
// ----------------------------------------------------------------------------
__device__ __forceinline__ void mma_bf16(float* c, const unsigned* a, const unsigned* b) {
    asm volatile(
        "mma.sync.aligned.m16n8k16.row.col.f32.bf16.bf16.f32 "
        "{%0,%1,%2,%3}, {%4,%5,%6,%7}, {%8,%9}, {%0,%1,%2,%3};"
        : "+f"(c[0]), "+f"(c[1]), "+f"(c[2]), "+f"(c[3])
        : "r"(a[0]), "r"(a[1]), "r"(a[2]), "r"(a[3]), "r"(b[0]), "r"(b[1]));
}
__device__ __forceinline__ void ldsm_x4(unsigned* r, unsigned addr) {
    asm volatile("ldmatrix.sync.aligned.m8n8.x4.shared.b16 {%0,%1,%2,%3}, [%4];"
        : "=r"(r[0]), "=r"(r[1]), "=r"(r[2]), "=r"(r[3]) : "r"(addr));
}
__device__ __forceinline__ void ldsm_x2(unsigned* r, unsigned addr) {
    asm volatile("ldmatrix.sync.aligned.m8n8.x2.shared.b16 {%0,%1}, [%2];"
        : "=r"(r[0]), "=r"(r[1]) : "r"(addr));
}

// dynamic SMEM partition (u32 units). Ping-pong buffers for A and B tiles.
#define U_AS_HI  0                 // 2 bufs x (64 rows x 20)
#define U_AS_LO  2560
#define U_BS_HI  5120              // 2 bufs x (128 rows x 20)
#define U_BS_LO  10240
#define U_ACT_HI 15360             // 64 rows x 260 (256 k-pairs + pad)
#define U_ACT_LO 32000
#define U_TOTAL  48640
#define SMEM_BYTES (U_TOTAL * 4)   // 194560

// ----------------------------------------------------------------------------
// Fused expert kernel: one 64-row slot tile per block, 256 threads (8 warps,
// warp grid 2m x 4n). 3-term bf16-split MMA (C += Ah*Bh + Ah*Bl + Al*Bh).
// Phase A: 8 passes over paired 64 gate + 64 up cols, K=1024, double-buffered
//          SMEM (1 sync/chunk), SiLU -> act SMEM (bf16 hi/lo).
// Phase B: 8 passes of 128 cols, K=512, A-frags straight from act SMEM via
//          ldmatrix; epilogue fused combine via atomicAdd(out[token], w*val).
// ----------------------------------------------------------------------------
__global__ void __launch_bounds__(256) fused_moe_kernel(
    const float* __restrict__ x, const float* __restrict__ wgu,
    const float* __restrict__ wd, float* __restrict__ out) {

    extern __shared__ unsigned sm[];
    const unsigned sbase = (unsigned)__cvta_generic_to_shared(sm);

    int bm = blockIdx.x;
    if (bm >= g_total_tiles) return;
    int e = 0;
    while (e < NE - 1 && g_tile_off[e + 1] <= bm) e++;
    int row_start  = g_offsets[e] + (bm - g_tile_off[e]) * TILE_M;
    int rows_valid = g_offsets[e + 1] - row_start;
    if (rows_valid > TILE_M) rows_valid = TILE_M;

    int tid  = threadIdx.x;
    int lane = tid & 31;
    int wid  = tid >> 5;
    int wm   = (wid >> 2) * 32;    // warp m offset (0/32)
    int wn4  = wid & 3;            // warp n slot
    int gq   = lane >> 2;
    int tq   = lane & 3;

    // ldmatrix lane geometry
    int lm_r = (lane & 7) + ((lane >> 3) & 1) * 8;  // row within 16 (x4)
    int lm_c = (lane >> 4) * 4;                     // k-pair offset (x4)
    int l16  = lane & 15;
    int lb_r = l16 & 7;                             // B row within 8 (x2)
    int lb_c = (l16 >> 3) * 4;                      // B k-pair offset (x2)

    // A global loader: row = tid>>2, 8-float granule = tid&3
    int arow = tid >> 2, g4 = tid & 3;
    int ar   = arow < rows_valid ? arow : 0;
    const float* afp = x + (size_t)g_row_token[row_start + ar] * HID + g4 * 8;
    int as_w = arow * 20 + g4 * 4;

    // Phase A B loader: 64 cols x 2 k-halves x {gate,up}
    int bnA  = tid & 63;
    int bkhA = (tid >> 6) & 1;
    int gup  = tid >> 7;
    int bs_wA = (gup * 64 + bnA) * 20 + bkhA * 8;

    // Phase B loader: 128 cols x 2 k-halves
    int bnB  = tid & 127;
    int bkhB = tid >> 7;
    int bs_wB = bnB * 20 + bkhB * 8;

    // per-thread ldmatrix byte offsets (add ks*32 and buffer bases at use)
    unsigned aoff[2], actoff[2];
    #pragma unroll
    for (int mi = 0; mi < 2; mi++) {
        aoff[mi]   = ((wm + mi * 16 + lm_r) * 20  + lm_c) * 4;
        actoff[mi] = ((wm + mi * 16 + lm_r) * 260 + lm_c) * 4;
    }
    unsigned boff = (lb_r * 20 + lb_c) * 4;

    const float* wgu_e = wgu + (size_t)e * HID * 1024;
    const float* wd_e  = wd + (size_t)e * INTER * 1024;

    // =========================== Phase A ===========================
    for (int nc = 0; nc < 8; nc++) {
        int bcolA = gup * 512 + nc * 64 + bnA;
        float accg[2][2][4], accu[2][2][4];
        #pragma unroll
        for (int mi = 0; mi < 2; mi++)
            #pragma unroll
            for (int ni = 0; ni < 2; ni++)
                #pragma unroll
                for (int q = 0; q < 4; q++) { accg[mi][ni][q] = 0.f; accu[mi][ni][q] = 0.f; }

        float4 a0v, a1v; float bv[16];

        auto load_chunk = [&](int kbase) {
            a0v = *(const float4*)(afp + kbase);
            a1v = *(const float4*)(afp + kbase + 4);
            const float* bp = wgu_e + (size_t)(kbase + bkhA * 16) * 1024 + bcolA;
            #pragma unroll
            for (int kk = 0; kk < 16; kk++) bv[kk] = bp[(size_t)kk * 1024];
        };
        auto stage = [&](int buf) {
            uint4 ha, la;
            split_pack(a0v.x, a0v.y, ha.x, la.x);
            split_pack(a0v.z, a0v.w, ha.y, la.y);
            split_pack(a1v.x, a1v.y, ha.z, la.z);
            split_pack(a1v.z, a1v.w, ha.w, la.w);
            *(uint4*)&sm[U_AS_HI + buf * 1280 + as_w] = ha;
            *(uint4*)&sm[U_AS_LO + buf * 1280 + as_w] = la;
            unsigned bh[8], bl[8];
            #pragma unroll
            for (int kp = 0; kp < 8; kp++)
                split_pack(bv[2 * kp], bv[2 * kp + 1], bh[kp], bl[kp]);
            *(uint4*)&sm[U_BS_HI + buf * 2560 + bs_wA]     = *(uint4*)&bh[0];
            *(uint4*)&sm[U_BS_HI + buf * 2560 + bs_wA + 4] = *(uint4*)&bh[4];
            *(uint4*)&sm[U_BS_LO + buf * 2560 + bs_wA]     = *(uint4*)&bl[0];
            *(uint4*)&sm[U_BS_LO + buf * 2560 + bs_wA + 4] = *(uint4*)&bl[4];
        };
        auto mma_stage = [&](int buf) {
            unsigned ah_b = sbase + (U_AS_HI + buf * 1280) * 4;
            unsigned al_b = sbase + (U_AS_LO + buf * 1280) * 4;
            unsigned bh_b = sbase + (U_BS_HI + buf * 2560) * 4;
            unsigned bl_b = sbase + (U_BS_LO + buf * 2560) * 4;
            #pragma unroll
            for (int ks = 0; ks < 2; ks++) {
                unsigned Ah[2][4], Al[2][4];
                #pragma unroll
                for (int mi = 0; mi < 2; mi++) {
                    ldsm_x4(Ah[mi], ah_b + aoff[mi] + ks * 32);
                    ldsm_x4(Al[mi], al_b + aoff[mi] + ks * 32);
                }
                #pragma unroll
                for (int ni = 0; ni < 2; ni++) {
                    unsigned ro = (unsigned)((wn4 * 16 + ni * 8) * 20) * 4 + boff + ks * 32;
                    unsigned Bgh[2], Bgl[2], Buh[2], Bul[2];
                    ldsm_x2(Bgh, bh_b + ro);
                    ldsm_x2(Bgl, bl_b + ro);
                    ldsm_x2(Buh, bh_b + ro + 64 * 20 * 4);
                    ldsm_x2(Bul, bl_b + ro + 64 * 20 * 4);
                    #pragma unroll
                    for (int mi = 0; mi < 2; mi++) {
                        mma_bf16(accg[mi][ni], Ah[mi], Bgh);
                        mma_bf16(accg[mi][ni], Ah[mi], Bgl);
                        mma_bf16(accg[mi][ni], Al[mi], Bgh);
                        mma_bf16(accu[mi][ni], Ah[mi], Buh);
                        mma_bf16(accu[mi][ni], Ah[mi], Bul);
                        mma_bf16(accu[mi][ni], Al[mi], Buh);
                    }
                }
            }
        };

        load_chunk(0);
        stage(0);
        __syncthreads();
        int cur = 0;
        for (int k0 = 0; k0 < HID; k0 += 32) {
            bool more = (k0 + 32 < HID);
            if (more) load_chunk(k0 + 32);
            mma_stage(cur);
            if (more) stage(cur ^ 1);
            __syncthreads();
            cur ^= 1;
        }

        // SiLU -> act SMEM (bf16 hi/lo pairs)
        #pragma unroll
        for (int mi = 0; mi < 2; mi++) {
            int r0 = wm + mi * 16 + gq, r1 = r0 + 8;
            #pragma unroll
            for (int ni = 0; ni < 2; ni++) {
                int cidx = nc * 32 + wn4 * 8 + ni * 4 + tq;
                float gA = accg[mi][ni][0], gB = accg[mi][ni][1];
                float p0 = gA / (1.f + expf(-gA)) * accu[mi][ni][0];
                float p1 = gB / (1.f + expf(-gB)) * accu[mi][ni][1];
                unsigned h, l;
                split_pack(p0, p1, h, l);
                sm[U_ACT_HI + r0 * 260 + cidx] = h;
                sm[U_ACT_LO + r0 * 260 + cidx] = l;
                gA = accg[mi][ni][2]; gB = accg[mi][ni][3];
                p0 = gA / (1.f + expf(-gA)) * accu[mi][ni][2];
                p1 = gB / (1.f + expf(-gB)) * accu[mi][ni][3];
                split_pack(p0, p1, h, l);
                sm[U_ACT_HI + r1 * 260 + cidx] = h;
                sm[U_ACT_LO + r1 * 260 + cidx] = l;
            }
        }
    }
    __syncthreads();   // act complete before Phase B reads

    // =========================== Phase B ===========================
    for (int nc2 = 0; nc2 < 8; nc2++) {
        int n0 = nc2 * 128;
        float acc[2][4][4];
        #pragma unroll
        for (int mi = 0; mi < 2; mi++)
            #pragma unroll
            for (int ni = 0; ni < 4; ni++)
                #pragma unroll
                for (int q = 0; q < 4; q++) acc[mi][ni][q] = 0.f;

        float bv[16];
        auto load_chunkB = [&](int kbase) {
            const float* bp = wd_e + (size_t)(kbase + bkhB * 16) * 1024 + n0 + bnB;
            #pragma unroll
            for (int kk = 0; kk < 16; kk++) bv[kk] = bp[(size_t)kk * 1024];
        };
        auto stageB = [&](int buf) {
            unsigned bh[8], bl[8];
            #pragma unroll
            for (int kp = 0; kp < 8; kp++)
                split_pack(bv[2 * kp], bv[2 * kp + 1], bh[kp], bl[kp]);
            *(uint4*)&sm[U_BS_HI + buf * 2560 + bs_wB]     = *(uint4*)&bh[0];
            *(uint4*)&sm[U_BS_HI + buf * 2560 + bs_wB + 4] = *(uint4*)&bh[4];
            *(uint4*)&sm[U_BS_LO + buf * 2560 + bs_wB]     = *(uint4*)&bl[0];
            *(uint4*)&sm[U_BS_LO + buf * 2560 + bs_wB + 4] = *(uint4*)&bl[4];
        };
        auto mma_stageB = [&](int buf, int k0) {
            unsigned bh_b = sbase + (U_BS_HI + buf * 2560) * 4;
            unsigned bl_b = sbase + (U_BS_LO + buf * 2560) * 4;
            unsigned acth = sbase + U_ACT_HI * 4 + (unsigned)(k0 >> 1) * 4;
            unsigned actl = sbase + U_ACT_LO * 4 + (unsigned)(k0 >> 1) * 4;
            #pragma unroll
            for (int ks = 0; ks < 2; ks++) {
                unsigned Ah[2][4], Al[2][4];
                #pragma unroll
                for (int mi = 0; mi < 2; mi++) {
                    ldsm_x4(Ah[mi], acth + actoff[mi] + ks * 32);
                    ldsm_x4(Al[mi], actl + actoff[mi] + ks * 32);
                }
                #pragma unroll
                for (int ni = 0; ni < 4; ni++) {
                    unsigned ro = (unsigned)((wn4 * 32 + ni * 8) * 20) * 4 + boff + ks * 32;
                    unsigned Bh[2], Bl[2];
                    ldsm_x2(Bh, bh_b + ro);
                    ldsm_x2(Bl, bl_b + ro);
                    #pragma unroll
                    for (int mi = 0; mi < 2; mi++) {
                        mma_bf16(acc[mi][ni], Ah[mi], Bh);
                        mma_bf16(acc[mi][ni], Ah[mi], Bl);
                        mma_bf16(acc[mi][ni], Al[mi], Bh);
                    }
                }
            }
        };

        load_chunkB(0);
        stageB(0);
        __syncthreads();
        int cur = 0;
        for (int k0 = 0; k0 < INTER; k0 += 32) {
            bool more = (k0 + 32 < INTER);
            if (more) load_chunkB(k0 + 32);
            mma_stageB(cur, k0);
            if (more) stageB(cur ^ 1);
            __syncthreads();
            cur ^= 1;
        }

        // fused combine: out[token] += w_slot * val
        #pragma unroll
        for (int mi = 0; mi < 2; mi++) {
            int r0 = wm + mi * 16 + gq, r1 = r0 + 8;
            bool v0 = r0 < rows_valid, v1 = r1 < rows_valid;
            int   t0v = 0, t1v = 0;
            float w0 = 0.f, w1 = 0.f;
            if (v0) { t0v = g_row_token[row_start + r0]; w0 = g_slot_w[row_start + r0]; }
            if (v1) { t1v = g_row_token[row_start + r1]; w1 = g_slot_w[row_start + r1]; }
            #pragma unroll
            for (int ni = 0; ni < 4; ni++) {
                int col = n0 + wn4 * 32 + ni * 8 + tq * 2;
                if (v0) {
                    float* o = &out[(size_t)t0v * 1024 + col];
                    atomicAdd(o,     w0 * acc[mi][ni][0]);
                    atomicAdd(o + 1, w0 * acc[mi][ni][1]);
                }
                if (v1) {
                    float* o = &out[(size_t)t1v * 1024 + col];
                    atomicAdd(o,     w1 * acc[mi][ni][2]);
                    atomicAdd(o + 1, w1 * acc[mi][ni][3]);
                }
            }
        }
    }
}

// ----------------------------------------------------------------------------
extern "C" void kernel_launch(void* const* d_in, const int* in_sizes, int n_in,
                              void* d_out, int out_size) {
    const float* x   = (const float*)d_in[0];   // [8192, 1024]
    const float* rw  = (const float*)d_in[1];   // [1024, 64]
    const float* wgu = (const float*)d_in[2];   // [64, 1024, 1024]
    const float* wd  = (const float*)d_in[3];   // [64, 512, 1024]
    float* out = (float*)d_out;                 // [8192, 1024]

    static bool attr_set = false;
    if (!attr_set) {
        cudaFuncSetAttribute(fused_moe_kernel,
                             cudaFuncAttributeMaxDynamicSharedMemorySize,
                             SMEM_BYTES);
        attr_set = true;
    }

    init_kernel<<<1, 64>>>();
    zero_out_kernel<<<(T_TOKENS * HID / 4) / 256, 256>>>(out);
    router_kernel<<<T_TOKENS / 16, 256>>>(x, rw);
    scan_kernel<<<1, 1>>>();
    scatter_kernel<<<TK / 256, 256>>>();
    fused_moe_kernel<<<MAX_TILES, 256, SMEM_BYTES>>>(x, wgu, wd, out);
}